// round 4
// baseline (speedup 1.0000x reference)
#include <cuda_runtime.h>
#include <cuda_bf16.h>
#include <cstdint>

// Problem constants
#define BDIM 2
#define VDIM 8
#define PDIM 4096
#define DDIM 1024
#define NREF 256
#define EN   16384
#define NCAND 8
#define NCT  128          // EN / 128 column tiles

// Scratch (device globals: allocation-free)
__device__ float g_pval[BDIM * NREF * NCT * 4 * 8];   // 8 MB
__device__ int   g_pidx[BDIM * NREF * NCT * 4 * 8];   // 8 MB
__device__ int   g_cand[BDIM * NREF * NCAND];
__device__ int   g_topk[BDIM * NREF * 4];
__device__ float g_accum[3];

__constant__ int c_ST[3] = {2, 4, 6};   // SHARED_TEACHER
__constant__ int c_SS[3] = {1, 2, 3};   // SHARED_STUDENT

__device__ __forceinline__ void ins8(float x, int e, float* v, int* id) {
    if (x <= v[7]) return;
    v[7] = x; id[7] = e;
    #pragma unroll
    for (int j = 7; j >= 1; j--) {
        if (v[j] > v[j - 1]) {
            float tv = v[j]; v[j] = v[j - 1]; v[j - 1] = tv;
            int ti = id[j]; id[j] = id[j - 1]; id[j - 1] = ti;
        }
    }
}

// ---------------------------------------------------------------------------
// K1: sim GEMM (mma.sync bf16, fp32 accum), fused f32->bf16 convert, fused
//     B-row norm, fused per-row top-8 candidate partials (no g_sim!).
// 128x128 block tile, BK=32, 2-stage smem pipeline, 8 warps, warp tile 64x32.
// ---------------------------------------------------------------------------
#define GBK 32
#define SROW 40                              // halves per smem row (32 + 8 pad)
#define STAGE_BYTES 20480                    // A 10240 + B 10240
#define GEMM_SMEM (2 * STAGE_BYTES)          // 40960; epilogue reuses as 64x129 f32

__global__ void __launch_bounds__(256, 2)
k_gemm(const float* __restrict__ teacher, const int* __restrict__ ref_perm) {
    extern __shared__ __align__(16) char dsmem[];
    __shared__ float s_inv[128];

    const int b     = blockIdx.z;
    const int rbase = blockIdx.y * 128;
    const int ct    = blockIdx.x;
    const int ebase = ct * 128;
    const int tid   = threadIdx.x;
    const int lane  = tid & 31;
    const int wid   = tid >> 5;
    const int wm    = (wid >> 2) * 64;
    const int wn    = (wid & 3) * 32;
    const uint32_t sbase = (uint32_t)__cvta_generic_to_shared(dsmem);

    // global loaders: thread t -> row t>>1, k-segment (t&1)*16
    const int lrow = tid >> 1;
    const int lseg = (tid & 1) * 16;

    const float* aptr = teacher + ((size_t)(b * VDIM) * PDIM + ref_perm[rbase + lrow]) * DDIM + lseg;
    const int v = 2 * (ebase >> 12) + 1;           // EXTRA_FRAMES {1,3,5,7}
    const int p = (ebase & (PDIM - 1)) + lrow;
    const float* bptr = teacher + ((size_t)(b * VDIM + v) * PDIM + p) * DDIM + lseg;

    float acc[4][4][4];
    #pragma unroll
    for (int i = 0; i < 4; i++)
        #pragma unroll
        for (int j = 0; j < 4; j++)
            #pragma unroll
            for (int k = 0; k < 4; k++) acc[i][j][k] = 0.f;

    uint2 pfa[4], pfb[4];
    float ssq = 0.f;

    // ldmatrix lane addressing (offsets within a stage)
    const int g  = lane >> 3;
    const int xr = (lane & 7) + (g & 1) * 8;
    const int xk = (g >> 1) * 8;
    uint32_t a_off[4], b_off[2];
    #pragma unroll
    for (int mi = 0; mi < 4; mi++)
        a_off[mi] = (uint32_t)((wm + mi * 16 + xr) * SROW + xk) * 2;
    #pragma unroll
    for (int nj = 0; nj < 2; nj++)
        b_off[nj] = 10240u + (uint32_t)((wn + nj * 16 + xr) * SROW + xk) * 2;

    // smem store offset (bytes within stage) for this thread's 4 uint2 stores
    const uint32_t st_a = (uint32_t)(lrow * SROW + lseg) * 2;
    const uint32_t st_b = st_a + 10240u;

    // initial prefetch (kt = 0)
    #pragma unroll
    for (int i = 0; i < 4; i++) {
        float4 xa = *(const float4*)(aptr + i * 4);
        float4 xb = *(const float4*)(bptr + i * 4);
        ssq += xb.x * xb.x + xb.y * xb.y + xb.z * xb.z + xb.w * xb.w;
        __nv_bfloat162 a0, a1, b0, b1;
        a0.x = __float2bfloat16(xa.x); a0.y = __float2bfloat16(xa.y);
        a1.x = __float2bfloat16(xa.z); a1.y = __float2bfloat16(xa.w);
        b0.x = __float2bfloat16(xb.x); b0.y = __float2bfloat16(xb.y);
        b1.x = __float2bfloat16(xb.z); b1.y = __float2bfloat16(xb.w);
        pfa[i] = make_uint2(*(uint32_t*)&a0, *(uint32_t*)&a1);
        pfb[i] = make_uint2(*(uint32_t*)&b0, *(uint32_t*)&b1);
    }

    for (int kt = 0; kt < DDIM / GBK; kt++) {
        const uint32_t stg = (kt & 1) * STAGE_BYTES;
        char* stage = dsmem + stg;
        #pragma unroll
        for (int i = 0; i < 4; i++) {
            *(uint2*)(stage + st_a + i * 8) = pfa[i];
            *(uint2*)(stage + st_b + i * 8) = pfb[i];
        }
        __syncthreads();

        if (kt + 1 < DDIM / GBK) {
            const float* ap = aptr + (kt + 1) * GBK;
            const float* bp = bptr + (kt + 1) * GBK;
            #pragma unroll
            for (int i = 0; i < 4; i++) {
                float4 xa = *(const float4*)(ap + i * 4);
                float4 xb = *(const float4*)(bp + i * 4);
                ssq += xb.x * xb.x + xb.y * xb.y + xb.z * xb.z + xb.w * xb.w;
                __nv_bfloat162 a0, a1, b0, b1;
                a0.x = __float2bfloat16(xa.x); a0.y = __float2bfloat16(xa.y);
                a1.x = __float2bfloat16(xa.z); a1.y = __float2bfloat16(xa.w);
                b0.x = __float2bfloat16(xb.x); b0.y = __float2bfloat16(xb.y);
                b1.x = __float2bfloat16(xb.z); b1.y = __float2bfloat16(xb.w);
                pfa[i] = make_uint2(*(uint32_t*)&a0, *(uint32_t*)&a1);
                pfb[i] = make_uint2(*(uint32_t*)&b0, *(uint32_t*)&b1);
            }
        }

        #pragma unroll
        for (int ks = 0; ks < GBK; ks += 16) {
            uint32_t af[4][4], bf[2][4];
            #pragma unroll
            for (int mi = 0; mi < 4; mi++) {
                asm volatile("ldmatrix.sync.aligned.m8n8.x4.shared.b16 {%0,%1,%2,%3}, [%4];"
                    : "=r"(af[mi][0]), "=r"(af[mi][1]), "=r"(af[mi][2]), "=r"(af[mi][3])
                    : "r"(sbase + stg + a_off[mi] + ks * 2));
            }
            #pragma unroll
            for (int nj = 0; nj < 2; nj++) {
                asm volatile("ldmatrix.sync.aligned.m8n8.x4.shared.b16 {%0,%1,%2,%3}, [%4];"
                    : "=r"(bf[nj][0]), "=r"(bf[nj][1]), "=r"(bf[nj][2]), "=r"(bf[nj][3])
                    : "r"(sbase + stg + b_off[nj] + ks * 2));
            }
            #pragma unroll
            for (int mi = 0; mi < 4; mi++) {
                #pragma unroll
                for (int nj = 0; nj < 4; nj++) {
                    uint32_t bb0 = bf[nj >> 1][nj & 1];
                    uint32_t bb1 = bf[nj >> 1][(nj & 1) + 2];
                    asm volatile(
                        "mma.sync.aligned.m16n8k16.row.col.f32.bf16.bf16.f32 "
                        "{%0,%1,%2,%3}, {%4,%5,%6,%7}, {%8,%9}, {%0,%1,%2,%3};"
                        : "+f"(acc[mi][nj][0]), "+f"(acc[mi][nj][1]),
                          "+f"(acc[mi][nj][2]), "+f"(acc[mi][nj][3])
                        : "r"(af[mi][0]), "r"(af[mi][1]), "r"(af[mi][2]), "r"(af[mi][3]),
                          "r"(bb0), "r"(bb1));
                }
            }
        }
    }

    // B-row inverse norms (exact, from f32): pair (2r, 2r+1)
    ssq += __shfl_xor_sync(0xffffffffu, ssq, 1);
    if ((tid & 1) == 0) s_inv[lrow] = 1.0f / fmaxf(sqrtf(ssq), 1e-12f);

    // epilogue: 2 chunks of 64 rows staged in smem; fused top-8 per 32 cols
    float (*C)[129] = (float (*)[129])dsmem;
    const int erow = tid & 63;
    const int q    = tid >> 6;

    #pragma unroll
    for (int chunk = 0; chunk < 2; chunk++) {
        __syncthreads();                       // smem free of previous use
        if ((wm >> 6) == chunk) {
            #pragma unroll
            for (int mi = 0; mi < 4; mi++) {
                int lr = mi * 16 + (lane >> 2);
                #pragma unroll
                for (int nj = 0; nj < 4; nj++) {
                    int cc = wn + nj * 8 + (lane & 3) * 2;
                    C[lr][cc]         = acc[mi][nj][0] * s_inv[cc];
                    C[lr][cc + 1]     = acc[mi][nj][1] * s_inv[cc + 1];
                    C[lr + 8][cc]     = acc[mi][nj][2] * s_inv[cc];
                    C[lr + 8][cc + 1] = acc[mi][nj][3] * s_inv[cc + 1];
                }
            }
        }
        __syncthreads();

        float bv[8]; int bi[8];
        #pragma unroll
        for (int j = 0; j < 8; j++) { bv[j] = -3.4e38f; bi[j] = 0; }
        #pragma unroll
        for (int j = 0; j < 32; j++) {
            int c = q * 32 + j;
            ins8(C[erow][c], ebase + c, bv, bi);
        }
        int gr = rbase + chunk * 64 + erow;
        size_t o = ((((size_t)(b * NREF + gr)) * NCT + ct) * 4 + q) * 8;
        #pragma unroll
        for (int j = 0; j < 8; j++) { g_pval[o + j] = bv[j]; g_pidx[o + j] = bi[j]; }
    }
}

// ---------------------------------------------------------------------------
// K2: merge 512 partial top-8s (NCT*4) per (b,r) -> 8 candidates
// ---------------------------------------------------------------------------
__global__ void __launch_bounds__(256)
k_topk2() {
    int r = blockIdx.x, b = blockIdx.y, tid = threadIdx.x;
    size_t base = ((size_t)(b * NREF + r)) * (NCT * 4 * 8);

    float v[8]; int id[8];
    #pragma unroll
    for (int j = 0; j < 8; j++) { v[j] = -3.4e38f; id[j] = 0; }
    for (int i = tid * 16; i < tid * 16 + 16; i++)
        ins8(g_pval[base + i], g_pidx[base + i], v, id);

    __shared__ float sv[2048];
    __shared__ int   si[2048];
    __shared__ float sv2[256];
    __shared__ int   si2[256];
    #pragma unroll
    for (int j = 0; j < 8; j++) { sv[tid * 8 + j] = v[j]; si[tid * 8 + j] = id[j]; }
    __syncthreads();

    if (tid < 32) {
        float v2[8]; int id2[8];
        #pragma unroll
        for (int j = 0; j < 8; j++) { v2[j] = -3.4e38f; id2[j] = 0; }
        for (int t = tid * 64; t < tid * 64 + 64; t++) ins8(sv[t], si[t], v2, id2);
        #pragma unroll
        for (int j = 0; j < 8; j++) { sv2[tid * 8 + j] = v2[j]; si2[tid * 8 + j] = id2[j]; }
    }
    __syncthreads();
    if (tid == 0) {
        float v3[8]; int id3[8];
        #pragma unroll
        for (int j = 0; j < 8; j++) { v3[j] = -3.4e38f; id3[j] = 0; }
        for (int t = 0; t < 256; t++) ins8(sv2[t], si2[t], v3, id3);
        #pragma unroll
        for (int j = 0; j < 8; j++) g_cand[(b * NREF + r) * NCAND + j] = id3[j];
    }
}

// ---------------------------------------------------------------------------
// K3: exact fp32 re-rank of the 8 candidates -> exact top-4 indices
// ---------------------------------------------------------------------------
__global__ void k_rerank(const float* __restrict__ teacher,
                         const int* __restrict__ ref_perm) {
    int r = blockIdx.x, b = blockIdx.y;
    int tid = threadIdx.x, w = tid >> 5, lane = tid & 31;

    if (r == 0 && b == 0 && tid < 3) g_accum[tid] = 0.f;

    int e = g_cand[(b * NREF + r) * NCAND + w];
    int v = 2 * (e >> 12) + 1, p = e & (PDIM - 1);
    const float* er = teacher + ((size_t)(b * VDIM + v) * PDIM + p) * DDIM;
    const float* rr = teacher + ((size_t)(b * VDIM) * PDIM + ref_perm[r]) * DDIM;

    float dot = 0.f, ss = 0.f;
    #pragma unroll
    for (int j = 0; j < 8; j++) {
        int idx = lane * 4 + j * 128;
        float4 x = *(const float4*)(er + idx);
        float4 y = *(const float4*)(rr + idx);
        dot += x.x * y.x + x.y * y.y + x.z * y.z + x.w * y.w;
        ss  += x.x * x.x + x.y * x.y + x.z * x.z + x.w * x.w;
    }
    #pragma unroll
    for (int o = 16; o; o >>= 1) {
        dot += __shfl_xor_sync(0xffffffffu, dot, o);
        ss  += __shfl_xor_sync(0xffffffffu, ss, o);
    }

    __shared__ float s_sim[NCAND];
    __shared__ int   s_e[NCAND];
    if (lane == 0) {
        s_sim[w] = dot / fmaxf(sqrtf(ss), 1e-12f);
        s_e[w] = e;
    }
    __syncthreads();

    if (tid == 0) {
        bool used[NCAND] = {false, false, false, false, false, false, false, false};
        #pragma unroll
        for (int j = 0; j < 4; j++) {
            int best = -1;
            float bvv = -3.4e38f; int be = 0x7fffffff;
            for (int t = 0; t < NCAND; t++) {
                if (used[t]) continue;
                if (s_sim[t] > bvv || (s_sim[t] == bvv && s_e[t] < be)) {
                    bvv = s_sim[t]; be = s_e[t]; best = t;
                }
            }
            used[best] = true;
            g_topk[(b * NREF + r) * 4 + j] = s_e[best];
        }
    }
}

// ---------------------------------------------------------------------------
// K4: KL + smooth-L1 losses. 64 threads (2 warps) per KL row-pair.
//   pairs [0,1536):      d1   (3 iters x B x 256)
//   pairs [1536,3584):   d2   (B x 256 x 4)  -- computed once
//   pairs [3584,9728):   d3   (3 iters x B x 256 x 4)
// ---------------------------------------------------------------------------
__global__ void __launch_bounds__(256)
k_loss(const float* __restrict__ teacher, const float* __restrict__ student,
       const int* __restrict__ ref_perm, const int* __restrict__ shared_perm) {
    __shared__ float sacc[3];
    __shared__ float r0[4][2], r1[4][2];
    int tid = threadIdx.x;
    if (tid < 3) sacc[tid] = 0.f;

    int grp  = tid >> 6;
    int sub  = tid & 63;
    int w2   = (tid >> 5) & 1;
    int lane = tid & 31;
    int w    = blockIdx.x * 4 + grp;

    const float *pa, *pb, *pc, *pd;
    int target;
    if (w < 1536) {
        target = 0;
        int i = w / 512, rem = w & 511;
        int b = rem >> 8, r = rem & 255;
        int rp = ref_perm[r], sp = shared_perm[r];
        pa = teacher + ((size_t)(b * VDIM) * PDIM + rp) * DDIM;
        pb = teacher + ((size_t)(b * VDIM + c_ST[i]) * PDIM + sp) * DDIM;
        pc = student + ((size_t)(b * 4) * PDIM + rp) * DDIM;
        pd = student + ((size_t)(b * 4 + c_SS[i]) * PDIM + sp) * DDIM;
    } else if (w < 3584) {
        target = 1;
        int t = w - 1536;
        int b = t >> 10, rem = t & 1023;
        int r = rem >> 2, k = rem & 3;
        int rp = ref_perm[r];
        int e = g_topk[((b << 8) + r) * 4 + k];
        int v = 2 * (e >> 12) + 1, p = e & (PDIM - 1);
        pa = teacher + ((size_t)(b * VDIM) * PDIM + rp) * DDIM;
        pc = student + ((size_t)(b * 4) * PDIM + rp) * DDIM;
        pb = pd = teacher + ((size_t)(b * VDIM + v) * PDIM + p) * DDIM;
    } else {
        target = 2;
        int t = w - 3584;
        int i = t >> 11, rem = t & 2047;
        int b = rem >> 10, r = (rem >> 2) & 255, k = rem & 3;
        int sp = shared_perm[r];
        int e = g_topk[((b << 8) + r) * 4 + k];
        int v = 2 * (e >> 12) + 1, p = e & (PDIM - 1);
        pa = teacher + ((size_t)(b * VDIM + c_ST[i]) * PDIM + sp) * DDIM;
        pc = student + ((size_t)(b * 4 + c_SS[i]) * PDIM + sp) * DDIM;
        pb = pd = teacher + ((size_t)(b * VDIM + v) * PDIM + p) * DDIM;
    }

    float dt[16], ds[16];
    bool same = (pb == pd);
    #pragma unroll
    for (int j = 0; j < 4; j++) {
        int idx = sub * 4 + j * 256;
        float4 A  = *(const float4*)(pa + idx);
        float4 Bv = *(const float4*)(pb + idx);
        float4 C  = *(const float4*)(pc + idx);
        float4 Dv = same ? Bv : *(const float4*)(pd + idx);
        dt[4 * j + 0] = A.x - Bv.x; dt[4 * j + 1] = A.y - Bv.y;
        dt[4 * j + 2] = A.z - Bv.z; dt[4 * j + 3] = A.w - Bv.w;
        ds[4 * j + 0] = C.x - Dv.x; ds[4 * j + 1] = C.y - Dv.y;
        ds[4 * j + 2] = C.z - Dv.z; ds[4 * j + 3] = C.w - Dv.w;
    }

    // max over 64 threads
    float mt = -3.4e38f, ms = -3.4e38f;
    #pragma unroll
    for (int i = 0; i < 16; i++) { mt = fmaxf(mt, dt[i]); ms = fmaxf(ms, ds[i]); }
    #pragma unroll
    for (int o = 16; o; o >>= 1) {
        mt = fmaxf(mt, __shfl_xor_sync(0xffffffffu, mt, o));
        ms = fmaxf(ms, __shfl_xor_sync(0xffffffffu, ms, o));
    }
    if (lane == 0) { r0[grp][w2] = mt; r1[grp][w2] = ms; }
    __syncthreads();
    mt = fmaxf(r0[grp][0], r0[grp][1]);
    ms = fmaxf(r1[grp][0], r1[grp][1]);

    // log-sum-exp over 64 threads
    float st = 0.f, ssum = 0.f;
    #pragma unroll
    for (int i = 0; i < 16; i++) { st += expf(dt[i] - mt); ssum += expf(ds[i] - ms); }
    #pragma unroll
    for (int o = 16; o; o >>= 1) {
        st   += __shfl_xor_sync(0xffffffffu, st, o);
        ssum += __shfl_xor_sync(0xffffffffu, ssum, o);
    }
    __syncthreads();
    if (lane == 0) { r0[grp][w2] = st; r1[grp][w2] = ssum; }
    __syncthreads();
    float lset = mt + logf(r0[grp][0] + r0[grp][1]);
    float lses = ms + logf(r1[grp][0] + r1[grp][1]);

    // sum p * (log_p - log_q) pieces over 64 threads
    float acc = 0.f;
    #pragma unroll
    for (int i = 0; i < 16; i++) acc += expf(dt[i] - lset) * (dt[i] - ds[i]);
    #pragma unroll
    for (int o = 16; o; o >>= 1) acc += __shfl_xor_sync(0xffffffffu, acc, o);
    __syncthreads();
    if (lane == 0) r0[grp][w2] = acc;
    __syncthreads();

    if (sub == 0) {
        float kl = (r0[grp][0] + r0[grp][1]) - lset + lses;
        float ax = fabsf(kl);
        float sl = (ax < 0.5f) ? kl * kl : (ax - 0.25f);   // smooth_l1, beta=0.5
        atomicAdd(&sacc[target], sl);
    }
    __syncthreads();
    if (tid < 3) atomicAdd(&g_accum[tid], sacc[tid]);
}

// ---------------------------------------------------------------------------
// K5: final combine:  sum_d1/1536 + sum_d2/2048 + sum_d3/6144
// ---------------------------------------------------------------------------
__global__ void k_final(float* __restrict__ out) {
    out[0] = g_accum[0] * (1.0f / 1536.0f)
           + g_accum[1] * (1.0f / 2048.0f)
           + g_accum[2] * (1.0f / 6144.0f);
}

// ---------------------------------------------------------------------------
extern "C" void kernel_launch(void* const* d_in, const int* in_sizes, int n_in,
                              void* d_out, int out_size) {
    const float* teacher     = (const float*)d_in[0];
    const float* student     = (const float*)d_in[1];
    const int*   ref_perm    = (const int*)d_in[2];
    const int*   shared_perm = (const int*)d_in[3];
    float* out = (float*)d_out;

    k_gemm<<<dim3(NCT, NREF / 128, BDIM), 256, GEMM_SMEM>>>(teacher, ref_perm);
    k_topk2<<<dim3(NREF, BDIM), 256>>>();
    k_rerank<<<dim3(NREF, BDIM), 256>>>(teacher, ref_perm);
    k_loss<<<9728 / 4, 256>>>(teacher, student, ref_perm, shared_perm);
    k_final<<<1, 1>>>(out);
}